// round 8
// baseline (speedup 1.0000x reference)
#include <cuda_runtime.h>

// ---------------------------------------------------------------------------
// Single-kernel formulation. B=512. CHUNK=4096.
//   conv layers: (C,H) = (64,27)(192,27)(384,13)(256,13)(256,13)
//   per-batch lens: 46656, 139968, 64896, 43264, 43264
//   fc: 4096 (masked 1024), 4096 (masked 1024), 1000 dense
//   chunks/layer: 12,35,16,11,11,1,1,1 -> 88
// ---------------------------------------------------------------------------
#define CHUNK   4096
#define NCHUNK  88
#define BPB     8              // batches per block
#define TPB     256
#define NB      512
#define NYGRP   (NB / BPB)     // 64

__device__ float g_scratch[NB * NCHUNK];
__device__ int   g_cnt[NYGRP];   // zero-init at load; last block re-zeros per replay

__device__ __forceinline__ int idx_at(const void* ip, bool is64, int k) {
    return is64 ? (int)((const long long*)ip)[k] : ((const int*)ip)[k];
}

// Coef build for a conv layer with COMPILE-TIME hh so the division lowers to
// reciprocal-multiply, not the generic slow int-div sequence.
template<int HH>
__device__ __forceinline__ void build_conv(float* s_coef, int base, int n,
                                           const float* __restrict__ mass,
                                           const float* __restrict__ W, int wOff)
{
    for (int p = threadIdx.x; p < n; p += TPB) {
        int q  = base + p;
        int c  = q / HH;                // magic-multiply at compile time
        int hw = q - c * HH;
        s_coef[p] = __ldg(mass + hw) * __ldg(W + wOff + c);
    }
}

// ---------------------------------------------------------------------------
// grid = (NCHUNK, NYGRP). Each block:
//   1) builds its 4096-float coef slice in smem (conv: mass*W; fc: scatter)
//   2) streams BPB=8 batch rows of its slice from HBM (__ldcs, evict-first)
//   3) block-reduces, writes 8 partials
//   4) last block of the y-group sums the 88 partials per batch (fixed
//      order -> deterministic), adds bias, writes out, resets counter.
// ---------------------------------------------------------------------------
__global__ void __launch_bounds__(TPB)
fused_dot(const float* __restrict__ f0, const float* __restrict__ f1,
          const float* __restrict__ f2, const float* __restrict__ f3,
          const float* __restrict__ f4, const float* __restrict__ c0,
          const float* __restrict__ c1, const float* __restrict__ c2,
          const float* __restrict__ m0, const float* __restrict__ m1,
          const float* __restrict__ m2, const float* __restrict__ m3,
          const float* __restrict__ m4,
          const float* __restrict__ W, const float* __restrict__ mfc,
          const void* __restrict__ i0, const void* __restrict__ i1,
          const float* __restrict__ bias, float* __restrict__ out)
{
    const int chunkStart[9] = {0, 12, 47, 63, 74, 85, 86, 87, 88};
    const int layerLen[8]   = {46656, 139968, 64896, 43264, 43264, 4096, 4096, 1000};

    __shared__ __align__(16) float s_coef[CHUNK];
    __shared__ float sred[BPB][TPB / 32];
    __shared__ int sIsLast;

    int chunk = blockIdx.x;
    int layer = 0;
#pragma unroll
    for (int l = 1; l < 8; l++) if (chunk >= chunkStart[l]) layer = l;

    int len  = layerLen[layer];
    int base = (chunk - chunkStart[layer]) * CHUNK;
    int n    = min(CHUNK, len - base);

    // ---- build coef slice in smem --------------------------------------
    switch (layer) {
        case 0: build_conv<729>(s_coef, base, n, m0, W,   0); break;
        case 1: build_conv<729>(s_coef, base, n, m1, W,  64); break;
        case 2: build_conv<169>(s_coef, base, n, m2, W, 256); break;
        case 3: build_conv<169>(s_coef, base, n, m3, W, 640); break;
        case 4: build_conv<169>(s_coef, base, n, m4, W, 896); break;
        case 5: case 6: {
            // fc0 / fc1: zero then scatter the 1024 selected slots (whole
            // 4096-slot layer fits one chunk: base==0, n==4096)
            for (int p = threadIdx.x; p < n; p += TPB) s_coef[p] = 0.0f;
            __syncthreads();
            const void* ip = (layer == 5) ? i0 : i1;
            int wBase = (layer == 5) ? 1152 : 2176;
            long long probe = ((const long long*)ip)[1];
            bool is64 = (probe >= 0 && probe < 4096);
            float s = __ldg(mfc);
            for (int k = threadIdx.x; k < 1024; k += TPB) {
                int v = idx_at(ip, is64, k);
                s_coef[v] = s * __ldg(W + wBase + k);
            }
            break;
        }
        default: {
            float s = __ldg(mfc);
            for (int p = threadIdx.x; p < n; p += TPB)
                s_coef[p] = s * __ldg(W + 3200 + p);
            break;
        }
    }
    __syncthreads();

    // ---- streaming dot over BPB batches --------------------------------
    const float* in;
    switch (layer) {
        case 0: in = f0; break; case 1: in = f1; break;
        case 2: in = f2; break; case 3: in = f3; break;
        case 4: in = f4; break; case 5: in = c0; break;
        case 6: in = c1; break; default: in = c2; break;
    }
    int b0 = blockIdx.y * BPB;
    const float*  p0  = in + (size_t)b0 * len + base;
    const float4* cf4 = (const float4*)s_coef;
    int n4 = n >> 2;                 // every chunk length is a multiple of 4

    float acc[BPB];
#pragma unroll
    for (int r = 0; r < BPB; r++) acc[r] = 0.f;

    for (int i = threadIdx.x; i < n4; i += TPB) {
        float4 cv = cf4[i];
#pragma unroll
        for (int r = 0; r < BPB; r++) {
            float4 v = __ldcs((const float4*)(p0 + (size_t)r * len) + i);
            acc[r] += cv.x*v.x + cv.y*v.y + cv.z*v.z + cv.w*v.w;
        }
    }

    // ---- block reduction ------------------------------------------------
#pragma unroll
    for (int off = 16; off > 0; off >>= 1)
#pragma unroll
        for (int r = 0; r < BPB; r++)
            acc[r] += __shfl_down_sync(0xFFFFFFFFu, acc[r], off);

    int warp = threadIdx.x >> 5, lane = threadIdx.x & 31;
    if (lane == 0)
#pragma unroll
        for (int r = 0; r < BPB; r++) sred[r][warp] = acc[r];
    __syncthreads();
    if (threadIdx.x < BPB) {
        float t = 0.f;
#pragma unroll
        for (int w = 0; w < TPB / 32; w++) t += sred[threadIdx.x][w];
        g_scratch[(size_t)(b0 + threadIdx.x) * NCHUNK + chunk] = t;
    }
    __threadfence();
    __syncthreads();
    if (threadIdx.x == 0) {
        int old = atomicAdd(&g_cnt[blockIdx.y], 1);
        sIsLast = (old == NCHUNK - 1);
    }
    __syncthreads();

    // ---- last block of this y-group finishes the 8 outputs --------------
    if (sIsLast) {
        if (warp < BPB) {
            const float* sc = g_scratch + (size_t)(b0 + warp) * NCHUNK;
            float t = 0.f;
            // fixed per-lane ascending order -> deterministic sum
            for (int j = lane; j < NCHUNK; j += 32) t += __ldcg(sc + j);
#pragma unroll
            for (int off = 16; off > 0; off >>= 1)
                t += __shfl_down_sync(0xFFFFFFFFu, t, off);
            if (lane == 0) out[b0 + warp] = t + __ldg(bias);
        }
        if (threadIdx.x == 0) g_cnt[blockIdx.y] = 0;   // ready for next replay
    }
}

// ---------------------------------------------------------------------------
// Host launcher. Inputs identified by element count (stable within groups).
// ---------------------------------------------------------------------------
extern "C" void kernel_launch(void* const* d_in, const int* in_sizes, int n_in,
                              void* d_out, int out_size)
{
    const float *f[5] = {0}, *fc[3] = {0}, *mass[5] = {0}, *W = 0, *bias = 0, *mfc = 0;
    const void  *idx[2] = {0};
    int nf34 = 0, nfc01 = 0, nidx = 0, n729 = 0, n169 = 0, nOne = 0;

    for (int i = 0; i < n_in; i++) {
        int sz = in_sizes[i];
        const void* p = d_in[i];
        if      (sz == 23887872) f[0] = (const float*)p;
        else if (sz == 71663616) f[1] = (const float*)p;
        else if (sz == 33226752) f[2] = (const float*)p;
        else if (sz == 22151168) { if (nf34 < 2) f[3 + nf34++] = (const float*)p; }
        else if (sz ==  2097152) { if (nfc01 < 2) fc[nfc01++] = (const float*)p; }
        else if (sz ==   512000) fc[2] = (const float*)p;
        else if (sz ==     1024) { if (nidx < 2) idx[nidx++] = p; }
        else if (sz ==     4200) W = (const float*)p;
        else if (sz ==      729) { if (n729 < 2) mass[n729++] = (const float*)p; }
        else if (sz ==      169) { if (n169 < 3) mass[2 + n169++] = (const float*)p; }
        else if (sz ==        1) { if (nOne++ == 0) mfc = (const float*)p; else bias = (const float*)p; }
    }

    fused_dot<<<dim3(NCHUNK, NYGRP), TPB>>>(
        f[0], f[1], f[2], f[3], f[4], fc[0], fc[1], fc[2],
        mass[0], mass[1], mass[2], mass[3], mass[4],
        W, mfc, idx[0], idx[1], bias, (float*)d_out);
}

// round 9
// speedup vs baseline: 1.1869x; 1.1869x over previous
#include <cuda_runtime.h>

// ---------------------------------------------------------------------------
// Single-kernel formulation. B=512. CHUNK=4096.
//   conv layers: (C,H) = (64,27)(192,27)(384,13)(256,13)(256,13)
//   per-batch lens: 46656, 139968, 64896, 43264, 43264
//   fc: 4096 (masked 1024), 4096 (masked 1024), 1000 dense
//   chunks/layer: 12,35,16,11,11,1,1,1 -> 88
// ---------------------------------------------------------------------------
#define CHUNK   4096
#define NCHUNK  88
#define BPB     8              // batches per block
#define TPB     256
#define NB      512
#define NYGRP   (NB / BPB)     // 64

__device__ float g_scratch[NB * NCHUNK];
__device__ int   g_cnt[NYGRP];   // zero-init at load; last block re-zeros per replay

__device__ __forceinline__ int idx_at(const void* ip, bool is64, int k) {
    return is64 ? (int)((const long long*)ip)[k] : ((const int*)ip)[k];
}

// Coef build with COMPILE-TIME hh -> reciprocal-multiply division.
template<int HH>
__device__ __forceinline__ void build_conv(float* s_coef, int base, int n,
                                           const float* __restrict__ mass,
                                           const float* __restrict__ W, int wOff)
{
    for (int p = threadIdx.x; p < n; p += TPB) {
        int q  = base + p;
        int c  = q / HH;
        int hw = q - c * HH;
        s_coef[p] = __ldg(mass + hw) * __ldg(W + wOff + c);
    }
}

// ---------------------------------------------------------------------------
// grid = (NCHUNK, NYGRP). __launch_bounds__(256, 4): 64-reg budget so the
// 8 in-flight float4 stream loads stay register-resident (MLP=8/thread).
// ---------------------------------------------------------------------------
__global__ void __launch_bounds__(TPB, 4)
fused_dot(const float* __restrict__ f0, const float* __restrict__ f1,
          const float* __restrict__ f2, const float* __restrict__ f3,
          const float* __restrict__ f4, const float* __restrict__ c0,
          const float* __restrict__ c1, const float* __restrict__ c2,
          const float* __restrict__ m0, const float* __restrict__ m1,
          const float* __restrict__ m2, const float* __restrict__ m3,
          const float* __restrict__ m4,
          const float* __restrict__ W, const float* __restrict__ mfc,
          const void* __restrict__ i0, const void* __restrict__ i1,
          const float* __restrict__ bias, float* __restrict__ out)
{
    const int chunkStart[9] = {0, 12, 47, 63, 74, 85, 86, 87, 88};
    const int layerLen[8]   = {46656, 139968, 64896, 43264, 43264, 4096, 4096, 1000};

    __shared__ __align__(16) float s_coef[CHUNK];
    __shared__ float sred[BPB][TPB / 32];
    __shared__ int sIsLast;

    int chunk = blockIdx.x;
    int layer = 0;
#pragma unroll
    for (int l = 1; l < 8; l++) if (chunk >= chunkStart[l]) layer = l;

    int len  = layerLen[layer];
    int base = (chunk - chunkStart[layer]) * CHUNK;
    int n    = min(CHUNK, len - base);

    // ---- build coef slice in smem --------------------------------------
    switch (layer) {
        case 0: build_conv<729>(s_coef, base, n, m0, W,   0); break;
        case 1: build_conv<729>(s_coef, base, n, m1, W,  64); break;
        case 2: build_conv<169>(s_coef, base, n, m2, W, 256); break;
        case 3: build_conv<169>(s_coef, base, n, m3, W, 640); break;
        case 4: build_conv<169>(s_coef, base, n, m4, W, 896); break;
        case 5: case 6: {
            // fc0 / fc1: zero then scatter the 1024 selected slots (layer
            // fits one chunk: base==0, n==4096)
            for (int p = threadIdx.x; p < n; p += TPB) s_coef[p] = 0.0f;
            __syncthreads();
            const void* ip = (layer == 5) ? i0 : i1;
            int wBase = (layer == 5) ? 1152 : 2176;
            long long probe = ((const long long*)ip)[1];
            bool is64 = (probe >= 0 && probe < 4096);
            float s = __ldg(mfc);
            for (int k = threadIdx.x; k < 1024; k += TPB) {
                int v = idx_at(ip, is64, k);
                s_coef[v] = s * __ldg(W + wBase + k);
            }
            break;
        }
        default: {
            float s = __ldg(mfc);
            for (int p = threadIdx.x; p < n; p += TPB)
                s_coef[p] = s * __ldg(W + 3200 + p);
            break;
        }
    }
    __syncthreads();

    // ---- streaming dot over BPB batches --------------------------------
    const float* in;
    switch (layer) {
        case 0: in = f0; break; case 1: in = f1; break;
        case 2: in = f2; break; case 3: in = f3; break;
        case 4: in = f4; break; case 5: in = c0; break;
        case 6: in = c1; break; default: in = c2; break;
    }
    int b0 = blockIdx.y * BPB;
    const float*  p0  = in + (size_t)b0 * len + base;
    const float4* cf4 = (const float4*)s_coef;
    int n4 = n >> 2;                 // every chunk length is a multiple of 4

    float acc[BPB];
#pragma unroll
    for (int r = 0; r < BPB; r++) acc[r] = 0.f;

    for (int i = threadIdx.x; i < n4; i += TPB) {
        // stage all 8 stream loads first (front-batched -> high MLP),
        // then the smem coef load and FMAs
        float4 v[BPB];
#pragma unroll
        for (int r = 0; r < BPB; r++)
            v[r] = __ldcs((const float4*)(p0 + (size_t)r * len) + i);
        float4 cv = cf4[i];
#pragma unroll
        for (int r = 0; r < BPB; r++)
            acc[r] += cv.x*v[r].x + cv.y*v[r].y + cv.z*v[r].z + cv.w*v[r].w;
    }

    // ---- block reduction ------------------------------------------------
#pragma unroll
    for (int off = 16; off > 0; off >>= 1)
#pragma unroll
        for (int r = 0; r < BPB; r++)
            acc[r] += __shfl_down_sync(0xFFFFFFFFu, acc[r], off);

    int warp = threadIdx.x >> 5, lane = threadIdx.x & 31;
    if (lane == 0)
#pragma unroll
        for (int r = 0; r < BPB; r++) sred[r][warp] = acc[r];
    __syncthreads();
    if (threadIdx.x < BPB) {
        float t = 0.f;
#pragma unroll
        for (int w = 0; w < TPB / 32; w++) t += sred[threadIdx.x][w];
        g_scratch[(size_t)(b0 + threadIdx.x) * NCHUNK + chunk] = t;
    }
    __threadfence();
    __syncthreads();
    if (threadIdx.x == 0) {
        int old = atomicAdd(&g_cnt[blockIdx.y], 1);
        sIsLast = (old == NCHUNK - 1);
    }
    __syncthreads();

    // ---- last block of this y-group finishes the 8 outputs --------------
    if (sIsLast) {
        if (warp < BPB) {
            const float* sc = g_scratch + (size_t)(b0 + warp) * NCHUNK;
            float t = 0.f;
            // fixed per-lane ascending order -> deterministic sum
            for (int j = lane; j < NCHUNK; j += 32) t += __ldcg(sc + j);
#pragma unroll
            for (int off = 16; off > 0; off >>= 1)
                t += __shfl_down_sync(0xFFFFFFFFu, t, off);
            if (lane == 0) out[b0 + warp] = t + __ldg(bias);
        }
        if (threadIdx.x == 0) g_cnt[blockIdx.y] = 0;   // ready for next replay
    }
}

// ---------------------------------------------------------------------------
// Host launcher. Inputs identified by element count (stable within groups).
// ---------------------------------------------------------------------------
extern "C" void kernel_launch(void* const* d_in, const int* in_sizes, int n_in,
                              void* d_out, int out_size)
{
    const float *f[5] = {0}, *fc[3] = {0}, *mass[5] = {0}, *W = 0, *bias = 0, *mfc = 0;
    const void  *idx[2] = {0};
    int nf34 = 0, nfc01 = 0, nidx = 0, n729 = 0, n169 = 0, nOne = 0;

    for (int i = 0; i < n_in; i++) {
        int sz = in_sizes[i];
        const void* p = d_in[i];
        if      (sz == 23887872) f[0] = (const float*)p;
        else if (sz == 71663616) f[1] = (const float*)p;
        else if (sz == 33226752) f[2] = (const float*)p;
        else if (sz == 22151168) { if (nf34 < 2) f[3 + nf34++] = (const float*)p; }
        else if (sz ==  2097152) { if (nfc01 < 2) fc[nfc01++] = (const float*)p; }
        else if (sz ==   512000) fc[2] = (const float*)p;
        else if (sz ==     1024) { if (nidx < 2) idx[nidx++] = p; }
        else if (sz ==     4200) W = (const float*)p;
        else if (sz ==      729) { if (n729 < 2) mass[n729++] = (const float*)p; }
        else if (sz ==      169) { if (n169 < 3) mass[2 + n169++] = (const float*)p; }
        else if (sz ==        1) { if (nOne++ == 0) mfc = (const float*)p; else bias = (const float*)p; }
    }

    fused_dot<<<dim3(NCHUNK, NYGRP), TPB>>>(
        f[0], f[1], f[2], f[3], f[4], fc[0], fc[1], fc[2],
        mass[0], mass[1], mass[2], mass[3], mass[4],
        W, mfc, idx[0], idx[1], bias, (float*)d_out);
}